// round 12
// baseline (speedup 1.0000x reference)
#include <cuda_runtime.h>
#include <cuda_bf16.h>
#include <stdint.h>

// Dataset-fixed: N=100000, T=25, DEGS=4, G=512, E=8000000
#define TPB    256
#define VEC    4                     // edges per thread per inner iteration
#define ITERS  4                     // inner iterations per tile
#define TILE   (TPB * VEC * ITERS)   // 4096 edges per tile
#define MAXGRID (148 * 8)            // persistent grid: full residency, one wave
#define NMAX   100000
#define TT     625                   // 25*25
#define GMAX   512

__device__ float4 g_nodes[NMAX];    // {pos.x, pos.y, pos.z, bitcast(atom_type)}
__device__ int    g_bnd[GMAX + 1];  // g_bnd[g] = first edge index of segment g
__device__ int    g_is64;           // 1 if index arrays are int64, 0 if int32

// ---------------------------------------------------------------------------
// Local dtype detection: int32 data read as int64 yields values >= N.
// ---------------------------------------------------------------------------
__device__ __forceinline__ int detect_is64(const long long* __restrict__ mapping, int N)
{
    bool ok64 = true;
    #pragma unroll
    for (int i = 0; i < 8; i++) {
        long long v = __ldg(mapping + i);
        if (v < 0 || v >= (long long)N) ok64 = false;
    }
    return ok64 ? 1 : 0;
}

__device__ __forceinline__ int read_flag() { return *(volatile int*)&g_is64; }

// ---------------------------------------------------------------------------
// Warp-cooperative lower_bound: 32-ary search, ~5 dependent rounds for E=8M.
// ---------------------------------------------------------------------------
template <typename IdxT>
__device__ __forceinline__ int warp_lower_bound(const IdxT* __restrict__ batch,
                                                int E, IdxT target, int lane)
{
    const unsigned full = 0xFFFFFFFFu;
    int lo = 0, len = E;
    while (len > 0) {
        int step  = (len + 31) >> 5;
        int probe = lo + lane * step;
        bool lt = false;
        if (lane * step < len)
            lt = (__ldg(batch + probe) < target);
        unsigned ballot = __ballot_sync(full, lt);
        if (ballot == 0) return lo;
        int kmax = 31 - __clz(ballot);
        int up   = (kmax + 1) * step; if (up > len) up = len;
        int nlo  = kmax * step + 1;
        lo  += nlo;
        len  = up - nlo;
    }
    return lo;
}

// ---------------------------------------------------------------------------
// Prep: detect dtype, zero output, pack node table, warp-parallel boundaries.
// ---------------------------------------------------------------------------
template <typename IdxT>
__device__ __forceinline__ void prep_body(const float* __restrict__ pos,
                                          const IdxT* __restrict__ atom_types,
                                          const IdxT* __restrict__ batch,
                                          float* __restrict__ out,
                                          int N, int E, int G)
{
    int i = blockIdx.x * blockDim.x + threadIdx.x;
    if (i < N) {
        float4 v;
        v.x = pos[3 * i + 0];
        v.y = pos[3 * i + 1];
        v.z = pos[3 * i + 2];
        v.w = __int_as_float((int)atom_types[i]);
        g_nodes[i] = v;
    }
    if (i < G) out[i] = 0.0f;

    int warpId = i >> 5;
    int lane   = i & 31;
    if (warpId <= G) {
        int b = warp_lower_bound<IdxT>(batch, E, (IdxT)warpId, lane);
        if (lane == 0) g_bnd[warpId] = b;
    }
}

__global__ void prep_kernel(const float* __restrict__ pos,
                            const void* __restrict__ atom_types,
                            const void* __restrict__ batch,
                            const void* __restrict__ mapping,
                            float* __restrict__ out,
                            int N, int E, int G)
{
    int is64 = detect_is64((const long long*)mapping, N);
    if (blockIdx.x == 0 && threadIdx.x == 0) g_is64 = is64;

    if (is64 == 0)
        prep_body<int>(pos, (const int*)atom_types, (const int*)batch, out, N, E, G);
    else
        prep_body<long long>(pos, (const long long*)atom_types, (const long long*)batch, out, N, E, G);
}

// ---------------------------------------------------------------------------
// Shared fragments
// ---------------------------------------------------------------------------
#define EDGE_V(II, JJ, VOUT)                                               \
    do {                                                                   \
        float4 p = __ldg(nodes + (II));                                    \
        float4 q = __ldg(nodes + (JJ));                                    \
        float dx = p.x - q.x, dy = p.y - q.y, dz = p.z - q.z;              \
        float r2 = fmaf(dx, dx, fmaf(dy, dy, dz * dz));                    \
        float x  = sqrtf(r2);                                              \
        int idx  = __float_as_int(p.w) * 25 + __float_as_int(q.w);         \
        float4 k = sk[idx];                                                \
        float  c = sv[idx];                                                \
        (VOUT) = fmaf(x, fmaf(x, fmaf(x, fmaf(x, k.w, k.z), k.y), k.x), c);\
    } while (0)

#define HANDLE1(EIDX, VVAL)                                                \
    do {                                                                   \
        if ((EIDX) >= bndEnd) {                                            \
            if (acc != 0.0f) atomicAdd(&out[seg], acc);                    \
            acc = 0.0f;                                                    \
            do { seg++; } while ((EIDX) >= sbnd[seg + 1]);                 \
            bndEnd = sbnd[seg + 1];                                        \
        }                                                                  \
        acc += (VVAL);                                                     \
    } while (0)

// Warp-aggregated final flush: one atomic per warp when segment is uniform.
__device__ __forceinline__ void flush_acc(float* __restrict__ out, int seg, float acc)
{
    const unsigned full = 0xFFFFFFFFu;
    int seg0 = __shfl_sync(full, seg, 0);
    bool uniform = __all_sync(full, seg == seg0);
    if (uniform) {
        #pragma unroll
        for (int o = 16; o > 0; o >>= 1)
            acc += __shfl_xor_sync(full, acc, o);
        if ((threadIdx.x & 31) == 0 && acc != 0.0f)
            atomicAdd(&out[seg0], acc);
    } else {
        if (acc != 0.0f) atomicAdd(&out[seg], acc);
    }
}

// ---------------------------------------------------------------------------
// Per-tile body (inner loop identical to R8)
// ---------------------------------------------------------------------------
__device__ __forceinline__ void do_tile32(int tile,
                                          const int* __restrict__ map0,
                                          const int* __restrict__ map1,
                                          float* __restrict__ out,
                                          int E, int G,
                                          const float4* sk, const float* sv,
                                          const int* sbnd)
{
    const int tid = threadIdx.x;

    int firstE = tile + tid * VEC;
    if (firstE >= E) firstE = E - 1;
    int lo = 0, hi = G - 1;
    while (lo < hi) {
        int mid = (lo + hi) >> 1;
        if (sbnd[mid + 1] <= firstE) lo = mid + 1; else hi = mid;
    }
    int   seg    = lo;
    int   bndEnd = sbnd[seg + 1];
    float acc    = 0.0f;

    const float4* __restrict__ nodes = g_nodes;

    if (tile + TILE <= E) {
        #pragma unroll
        for (int it = 0; it < ITERS; ++it) {
            const int e = tile + it * (TPB * VEC) + tid * VEC;
            int4 ia = __ldcs((const int4*)(map0 + e));
            int4 ja = __ldcs((const int4*)(map1 + e));

            float V0, V1, V2, V3;
            EDGE_V(ia.x, ja.x, V0);
            EDGE_V(ia.y, ja.y, V1);
            EDGE_V(ia.z, ja.z, V2);
            EDGE_V(ia.w, ja.w, V3);

            if (e + 3 < bndEnd) {
                acc += (V0 + V1) + (V2 + V3);
            } else {
                HANDLE1(e + 0, V0);
                HANDLE1(e + 1, V1);
                HANDLE1(e + 2, V2);
                HANDLE1(e + 3, V3);
            }
        }
    } else {
        for (int it = 0; it < ITERS; ++it) {
            int e = tile + it * (TPB * VEC) + tid * VEC;
            for (int kk = 0; kk < VEC; ++kk) {
                int ee = e + kk;
                if (ee >= E) break;
                int ii = __ldcs(map0 + ee);
                int jj = __ldcs(map1 + ee);
                float V;
                EDGE_V(ii, jj, V);
                HANDLE1(ee, V);
            }
        }
    }

    flush_acc(out, seg, acc);
}

// ---------------------------------------------------------------------------
// Persistent int32 edge kernel: tables loaded once, grid-stride over tiles
// ---------------------------------------------------------------------------
__global__ void __launch_bounds__(TPB, 8)
edge_kernel32(const int* __restrict__ map0,
              const int* __restrict__ map1,
              const float* __restrict__ ks,     // [4,25,25]
              const float* __restrict__ v0t,    // [25,25]
              float* __restrict__ out,
              int E, int G, int nTiles)
{
    if (read_flag() != 0) return;

    __shared__ float4 sk[TT];
    __shared__ float  sv[TT];
    __shared__ int    sbnd[GMAX + 1];

    const int tid = threadIdx.x;
    for (int i = tid; i < TT; i += TPB) {
        sk[i] = make_float4(ks[i], ks[TT + i], ks[2 * TT + i], ks[3 * TT + i]);
        sv[i] = v0t[i];
    }
    for (int i = tid; i <= G; i += TPB) sbnd[i] = g_bnd[i];
    __syncthreads();

    for (int t = blockIdx.x; t < nTiles; t += gridDim.x)
        do_tile32(t * TILE, map0, map1, out, E, G, sk, sv, sbnd);
}

// ---------------------------------------------------------------------------
// Persistent int64 fallback (dead case: 1184 blocks read flag and exit)
// ---------------------------------------------------------------------------
__global__ void __launch_bounds__(TPB)
edge_kernel64(const long long* __restrict__ map0,
              const long long* __restrict__ map1,
              const float* __restrict__ ks,
              const float* __restrict__ v0t,
              float* __restrict__ out,
              int E, int G, int nTiles)
{
    if (read_flag() != 1) return;

    __shared__ float4 sk[TT];
    __shared__ float  sv[TT];
    __shared__ int    sbnd[GMAX + 1];

    const int tid = threadIdx.x;
    for (int i = tid; i < TT; i += TPB) {
        sk[i] = make_float4(ks[i], ks[TT + i], ks[2 * TT + i], ks[3 * TT + i]);
        sv[i] = v0t[i];
    }
    for (int i = tid; i <= G; i += TPB) sbnd[i] = g_bnd[i];
    __syncthreads();

    const float4* __restrict__ nodes = g_nodes;

    for (int t = blockIdx.x; t < nTiles; t += gridDim.x) {
        const int tile = t * TILE;

        int firstE = tile + tid * VEC;
        if (firstE >= E) firstE = E - 1;
        int lo = 0, hi = G - 1;
        while (lo < hi) {
            int mid = (lo + hi) >> 1;
            if (sbnd[mid + 1] <= firstE) lo = mid + 1; else hi = mid;
        }
        int   seg    = lo;
        int   bndEnd = sbnd[seg + 1];
        float acc    = 0.0f;

        for (int it = 0; it < ITERS; ++it) {
            int e = tile + it * (TPB * VEC) + tid * VEC;
            if (e >= E) break;
            if (e + VEC <= E) {
                longlong2 a0 = __ldcs((const longlong2*)(map0 + e));
                longlong2 a1 = __ldcs((const longlong2*)(map0 + e + 2));
                longlong2 b0 = __ldcs((const longlong2*)(map1 + e));
                longlong2 b1 = __ldcs((const longlong2*)(map1 + e + 2));
                float V0, V1, V2, V3;
                EDGE_V((int)a0.x, (int)b0.x, V0);
                EDGE_V((int)a0.y, (int)b0.y, V1);
                EDGE_V((int)a1.x, (int)b1.x, V2);
                EDGE_V((int)a1.y, (int)b1.y, V3);
                if (e + 3 < bndEnd) {
                    acc += (V0 + V1) + (V2 + V3);
                } else {
                    HANDLE1(e + 0, V0);
                    HANDLE1(e + 1, V1);
                    HANDLE1(e + 2, V2);
                    HANDLE1(e + 3, V3);
                }
            } else {
                for (int kk = 0; kk < VEC; ++kk) {
                    int ee = e + kk;
                    if (ee >= E) break;
                    int ii = (int)__ldcs(map0 + ee);
                    int jj = (int)__ldcs(map1 + ee);
                    float V;
                    EDGE_V(ii, jj, V);
                    HANDLE1(ee, V);
                }
            }
        }
        if (acc != 0.0f) atomicAdd(&out[seg], acc);
    }
}

// ---------------------------------------------------------------------------
// Launch
// ---------------------------------------------------------------------------
extern "C" void kernel_launch(void* const* d_in, const int* in_sizes, int n_in,
                              void* d_out, int out_size)
{
    const float* pos = (const float*)d_in[0];
    const float* ks  = (const float*)d_in[1];
    const float* v0t = (const float*)d_in[2];
    const void*  mapping    = d_in[3];
    const void*  atom_types = d_in[4];
    const void*  batch      = d_in[5];

    const int N = in_sizes[0] / 3;
    const int E = in_sizes[3] / 2;
    const int G = out_size;

    float* out = (float*)d_out;

    int prepThreads = (N > (G + 1) * 32) ? N : (G + 1) * 32;
    int prepBlocks  = (prepThreads + TPB - 1) / TPB;
    prep_kernel<<<prepBlocks, TPB>>>(pos, atom_types, batch, mapping, out, N, E, G);

    int nTiles = (E + TILE - 1) / TILE;
    int grid   = nTiles < MAXGRID ? nTiles : MAXGRID;
    edge_kernel32<<<grid, TPB>>>(
        (const int*)mapping, (const int*)mapping + E, ks, v0t, out, E, G, nTiles);
    edge_kernel64<<<grid, TPB>>>(
        (const long long*)mapping, (const long long*)mapping + E, ks, v0t, out, E, G, nTiles);
}

// round 13
// speedup vs baseline: 1.0230x; 1.0230x over previous
#include <cuda_runtime.h>
#include <cuda_bf16.h>
#include <stdint.h>

// Dataset-fixed: N=100000, T=25, DEGS=4, G=512, E=8000000
#define TPB    256
#define VEC    4                     // edges per thread per inner iteration
#define ITERS  4                     // inner iterations per tile
#define TILE   (TPB * VEC * ITERS)   // 4096 edges per block
#define NMAX   100000
#define TT     625                   // 25*25

__device__ float4 g_nodes[NMAX];    // {pos.x, pos.y, pos.z, bitcast(atom_type)}
__device__ int    g_is64;           // 1 if index arrays are int64, 0 if int32

// ---------------------------------------------------------------------------
// Local dtype detection: int32 data read as int64 yields values >= N.
// ---------------------------------------------------------------------------
__device__ __forceinline__ int detect_is64(const long long* __restrict__ mapping, int N)
{
    bool ok64 = true;
    #pragma unroll
    for (int i = 0; i < 8; i++) {
        long long v = __ldg(mapping + i);
        if (v < 0 || v >= (long long)N) ok64 = false;
    }
    return ok64 ? 1 : 0;
}

__device__ __forceinline__ int read_flag() { return *(volatile int*)&g_is64; }

// ---------------------------------------------------------------------------
// Prep: detect dtype, zero output, pack node table. (No boundary search —
// segment ids are read directly from mapping_batch in the edge kernels.)
// ---------------------------------------------------------------------------
template <typename IdxT>
__device__ __forceinline__ void prep_body(const float* __restrict__ pos,
                                          const IdxT* __restrict__ atom_types,
                                          float* __restrict__ out,
                                          int N, int G)
{
    int i = blockIdx.x * blockDim.x + threadIdx.x;
    if (i < N) {
        float4 v;
        v.x = pos[3 * i + 0];
        v.y = pos[3 * i + 1];
        v.z = pos[3 * i + 2];
        v.w = __int_as_float((int)atom_types[i]);
        g_nodes[i] = v;
    }
    if (i < G) out[i] = 0.0f;
}

__global__ void prep_kernel(const float* __restrict__ pos,
                            const void* __restrict__ atom_types,
                            const void* __restrict__ mapping,
                            float* __restrict__ out,
                            int N, int G)
{
    int is64 = detect_is64((const long long*)mapping, N);
    if (blockIdx.x == 0 && threadIdx.x == 0) g_is64 = is64;

    if (is64 == 0)
        prep_body<int>(pos, (const int*)atom_types, out, N, G);
    else
        prep_body<long long>(pos, (const long long*)atom_types, out, N, G);
}

// ---------------------------------------------------------------------------
// Shared fragments
// ---------------------------------------------------------------------------
#define EDGE_V(II, JJ, VOUT)                                               \
    do {                                                                   \
        float4 p = __ldg(nodes + (II));                                    \
        float4 q = __ldg(nodes + (JJ));                                    \
        float dx = p.x - q.x, dy = p.y - q.y, dz = p.z - q.z;              \
        float r2 = fmaf(dx, dx, fmaf(dy, dy, dz * dz));                    \
        float x  = sqrtf(r2);                                              \
        int idx  = __float_as_int(p.w) * 25 + __float_as_int(q.w);         \
        float4 k = sk[idx];                                                \
        float  c = sv[idx];                                                \
        (VOUT) = fmaf(x, fmaf(x, fmaf(x, fmaf(x, k.w, k.z), k.y), k.x), c);\
    } while (0)

// Segment handling via direct batch value: flush accumulator on change.
// batch is sorted, so per-thread seg is non-decreasing.
#define HANDLE1(BI, VVAL)                                                  \
    do {                                                                   \
        if ((BI) != seg) {                                                 \
            if (acc != 0.0f) atomicAdd(&out[seg], acc);                    \
            acc = 0.0f;                                                    \
            seg = (BI);                                                    \
        }                                                                  \
        acc += (VVAL);                                                     \
    } while (0)

// Warp-aggregated final flush: one atomic per warp when segment is uniform.
__device__ __forceinline__ void flush_acc(float* __restrict__ out, int seg, float acc)
{
    const unsigned full = 0xFFFFFFFFu;
    int seg0 = __shfl_sync(full, seg, 0);
    bool uniform = __all_sync(full, seg == seg0);
    if (uniform) {
        #pragma unroll
        for (int o = 16; o > 0; o >>= 1)
            acc += __shfl_xor_sync(full, acc, o);
        if ((threadIdx.x & 31) == 0 && acc != 0.0f && seg0 >= 0)
            atomicAdd(&out[seg0], acc);
    } else {
        if (acc != 0.0f && seg >= 0) atomicAdd(&out[seg], acc);
    }
}

// ---------------------------------------------------------------------------
// Main int32 edge kernel — R8 inner loop, boundary machinery replaced by
// a streamed coalesced read of mapping_batch.
// ---------------------------------------------------------------------------
__global__ void __launch_bounds__(TPB, 8)
edge_kernel32(const int* __restrict__ map0,
              const int* __restrict__ map1,
              const int* __restrict__ batch,
              const float* __restrict__ ks,     // [4,25,25]
              const float* __restrict__ v0t,    // [25,25]
              float* __restrict__ out,
              int E)
{
    if (read_flag() != 0) return;

    __shared__ float4 sk[TT];
    __shared__ float  sv[TT];

    const int tid = threadIdx.x;
    for (int i = tid; i < TT; i += TPB) {
        sk[i] = make_float4(ks[i], ks[TT + i], ks[2 * TT + i], ks[3 * TT + i]);
        sv[i] = v0t[i];
    }
    __syncthreads();

    const int tile = blockIdx.x * TILE;
    if (tile >= E) return;

    int   seg = -1;      // sentinel: first HANDLE always sets it
    float acc = 0.0f;

    const float4* __restrict__ nodes = g_nodes;

    if (tile + TILE <= E) {
        #pragma unroll
        for (int it = 0; it < ITERS; ++it) {
            const int e = tile + it * (TPB * VEC) + tid * VEC;
            int4 ia = __ldcs((const int4*)(map0 + e));
            int4 ja = __ldcs((const int4*)(map1 + e));
            int4 bt = __ldcs((const int4*)(batch + e));

            float V0, V1, V2, V3;
            EDGE_V(ia.x, ja.x, V0);
            EDGE_V(ia.y, ja.y, V1);
            EDGE_V(ia.z, ja.z, V2);
            EDGE_V(ia.w, ja.w, V3);

            if (bt.w == seg) {                 // sorted => whole group == seg
                acc += (V0 + V1) + (V2 + V3);
            } else {
                HANDLE1(bt.x, V0);
                HANDLE1(bt.y, V1);
                HANDLE1(bt.z, V2);
                HANDLE1(bt.w, V3);
            }
        }
    } else {
        for (int it = 0; it < ITERS; ++it) {
            int e = tile + it * (TPB * VEC) + tid * VEC;
            for (int kk = 0; kk < VEC; ++kk) {
                int ee = e + kk;
                if (ee >= E) break;
                int ii = __ldcs(map0 + ee);
                int jj = __ldcs(map1 + ee);
                int bi = __ldcs(batch + ee);
                float V;
                EDGE_V(ii, jj, V);
                HANDLE1(bi, V);
            }
        }
    }

    flush_acc(out, seg, acc);
}

// ---------------------------------------------------------------------------
// int64 fallback (early-exits when data is int32)
// ---------------------------------------------------------------------------
__global__ void __launch_bounds__(TPB)
edge_kernel64(const long long* __restrict__ map0,
              const long long* __restrict__ map1,
              const long long* __restrict__ batch,
              const float* __restrict__ ks,
              const float* __restrict__ v0t,
              float* __restrict__ out,
              int E)
{
    if (read_flag() != 1) return;

    __shared__ float4 sk[TT];
    __shared__ float  sv[TT];

    const int tid = threadIdx.x;
    for (int i = tid; i < TT; i += TPB) {
        sk[i] = make_float4(ks[i], ks[TT + i], ks[2 * TT + i], ks[3 * TT + i]);
        sv[i] = v0t[i];
    }
    __syncthreads();

    const int tile = blockIdx.x * TILE;
    if (tile >= E) return;

    int   seg = -1;
    float acc = 0.0f;

    const float4* __restrict__ nodes = g_nodes;

    for (int it = 0; it < ITERS; ++it) {
        int e = tile + it * (TPB * VEC) + tid * VEC;
        if (e >= E) break;
        if (e + VEC <= E) {
            longlong2 a0 = __ldcs((const longlong2*)(map0 + e));
            longlong2 a1 = __ldcs((const longlong2*)(map0 + e + 2));
            longlong2 b0 = __ldcs((const longlong2*)(map1 + e));
            longlong2 b1 = __ldcs((const longlong2*)(map1 + e + 2));
            longlong2 c0 = __ldcs((const longlong2*)(batch + e));
            longlong2 c1 = __ldcs((const longlong2*)(batch + e + 2));
            float V0, V1, V2, V3;
            EDGE_V((int)a0.x, (int)b0.x, V0);
            EDGE_V((int)a0.y, (int)b0.y, V1);
            EDGE_V((int)a1.x, (int)b1.x, V2);
            EDGE_V((int)a1.y, (int)b1.y, V3);
            if ((int)c1.y == seg) {
                acc += (V0 + V1) + (V2 + V3);
            } else {
                HANDLE1((int)c0.x, V0);
                HANDLE1((int)c0.y, V1);
                HANDLE1((int)c1.x, V2);
                HANDLE1((int)c1.y, V3);
            }
        } else {
            for (int kk = 0; kk < VEC; ++kk) {
                int ee = e + kk;
                if (ee >= E) break;
                int ii = (int)__ldcs(map0 + ee);
                int jj = (int)__ldcs(map1 + ee);
                int bi = (int)__ldcs(batch + ee);
                float V;
                EDGE_V(ii, jj, V);
                HANDLE1(bi, V);
            }
        }
    }
    flush_acc(out, seg, acc);
}

// ---------------------------------------------------------------------------
// Launch
// ---------------------------------------------------------------------------
extern "C" void kernel_launch(void* const* d_in, const int* in_sizes, int n_in,
                              void* d_out, int out_size)
{
    const float* pos = (const float*)d_in[0];
    const float* ks  = (const float*)d_in[1];
    const float* v0t = (const float*)d_in[2];
    const void*  mapping    = d_in[3];
    const void*  atom_types = d_in[4];
    const void*  batch      = d_in[5];

    const int N = in_sizes[0] / 3;
    const int E = in_sizes[3] / 2;
    const int G = out_size;

    float* out = (float*)d_out;

    int prepThreads = (N > G) ? N : G;
    int prepBlocks  = (prepThreads + TPB - 1) / TPB;
    prep_kernel<<<prepBlocks, TPB>>>(pos, atom_types, mapping, out, N, G);

    int blocks = (E + TILE - 1) / TILE;
    edge_kernel32<<<blocks, TPB>>>(
        (const int*)mapping, (const int*)mapping + E, (const int*)batch,
        ks, v0t, out, E);
    edge_kernel64<<<blocks, TPB>>>(
        (const long long*)mapping, (const long long*)mapping + E, (const long long*)batch,
        ks, v0t, out, E);
}

// round 14
// speedup vs baseline: 1.1010x; 1.0763x over previous
#include <cuda_runtime.h>
#include <cuda_bf16.h>
#include <stdint.h>

// Dataset-fixed: N=100000, T=25, DEGS=4, G=512, E=8000000, indices int32
#define TPB    256
#define VEC    4                     // edges per thread per inner iteration
#define ITERS  4                     // inner iterations per tile
#define TILE   (TPB * VEC * ITERS)   // 4096 edges per block
#define NMAX   100000
#define TT     625                   // 25*25

__device__ float4 g_nodes[NMAX];    // {pos.x, pos.y, pos.z, bitcast(atom_type)}

// ---------------------------------------------------------------------------
// Prep: zero output, pack node table.
// ---------------------------------------------------------------------------
__global__ void prep_kernel(const float* __restrict__ pos,
                            const int* __restrict__ atom_types,
                            float* __restrict__ out,
                            int N, int G)
{
    int i = blockIdx.x * blockDim.x + threadIdx.x;
    if (i < N) {
        float4 v;
        v.x = pos[3 * i + 0];
        v.y = pos[3 * i + 1];
        v.z = pos[3 * i + 2];
        v.w = __int_as_float(atom_types[i]);
        g_nodes[i] = v;
    }
    if (i < G) out[i] = 0.0f;
}

// ---------------------------------------------------------------------------
// Shared fragments
// ---------------------------------------------------------------------------
#define EDGE_V(II, JJ, VOUT)                                               \
    do {                                                                   \
        float4 p = __ldg(nodes + (II));                                    \
        float4 q = __ldg(nodes + (JJ));                                    \
        float dx = p.x - q.x, dy = p.y - q.y, dz = p.z - q.z;              \
        float r2 = fmaf(dx, dx, fmaf(dy, dy, dz * dz));                    \
        float x  = sqrtf(r2);                                              \
        int idx  = __float_as_int(p.w) * 25 + __float_as_int(q.w);         \
        float4 k = sk[idx];                                                \
        float  c = sv[idx];                                                \
        (VOUT) = fmaf(x, fmaf(x, fmaf(x, fmaf(x, k.w, k.z), k.y), k.x), c);\
    } while (0)

// Segment handling via direct batch value: flush accumulator on change.
// batch is sorted, so per-thread seg is non-decreasing.
#define HANDLE1(BI, VVAL)                                                  \
    do {                                                                   \
        if ((BI) != seg) {                                                 \
            if (acc != 0.0f) atomicAdd(&out[seg], acc);                    \
            acc = 0.0f;                                                    \
            seg = (BI);                                                    \
        }                                                                  \
        acc += (VVAL);                                                     \
    } while (0)

// Warp-aggregated final flush: one atomic per warp when segment is uniform.
__device__ __forceinline__ void flush_acc(float* __restrict__ out, int seg, float acc)
{
    const unsigned full = 0xFFFFFFFFu;
    int seg0 = __shfl_sync(full, seg, 0);
    bool uniform = __all_sync(full, seg == seg0);
    if (uniform) {
        #pragma unroll
        for (int o = 16; o > 0; o >>= 1)
            acc += __shfl_xor_sync(full, acc, o);
        if ((threadIdx.x & 31) == 0 && acc != 0.0f && seg0 >= 0)
            atomicAdd(&out[seg0], acc);
    } else {
        if (acc != 0.0f && seg >= 0) atomicAdd(&out[seg], acc);
    }
}

// ---------------------------------------------------------------------------
// Edge kernel (int32): R13 body, flag machinery removed
// ---------------------------------------------------------------------------
__global__ void __launch_bounds__(TPB, 8)
edge_kernel(const int* __restrict__ map0,
            const int* __restrict__ map1,
            const int* __restrict__ batch,
            const float* __restrict__ ks,     // [4,25,25]
            const float* __restrict__ v0t,    // [25,25]
            float* __restrict__ out,
            int E)
{
    __shared__ float4 sk[TT];
    __shared__ float  sv[TT];

    const int tid = threadIdx.x;
    for (int i = tid; i < TT; i += TPB) {
        sk[i] = make_float4(ks[i], ks[TT + i], ks[2 * TT + i], ks[3 * TT + i]);
        sv[i] = v0t[i];
    }
    __syncthreads();

    const int tile = blockIdx.x * TILE;
    if (tile >= E) return;

    int   seg = -1;      // sentinel: first HANDLE always sets it
    float acc = 0.0f;

    const float4* __restrict__ nodes = g_nodes;

    if (tile + TILE <= E) {
        #pragma unroll
        for (int it = 0; it < ITERS; ++it) {
            const int e = tile + it * (TPB * VEC) + tid * VEC;
            int4 ia = __ldcs((const int4*)(map0 + e));
            int4 ja = __ldcs((const int4*)(map1 + e));
            int4 bt = __ldcs((const int4*)(batch + e));

            float V0, V1, V2, V3;
            EDGE_V(ia.x, ja.x, V0);
            EDGE_V(ia.y, ja.y, V1);
            EDGE_V(ia.z, ja.z, V2);
            EDGE_V(ia.w, ja.w, V3);

            if (bt.w == seg) {                 // sorted => whole group == seg
                acc += (V0 + V1) + (V2 + V3);
            } else {
                HANDLE1(bt.x, V0);
                HANDLE1(bt.y, V1);
                HANDLE1(bt.z, V2);
                HANDLE1(bt.w, V3);
            }
        }
    } else {
        for (int it = 0; it < ITERS; ++it) {
            int e = tile + it * (TPB * VEC) + tid * VEC;
            for (int kk = 0; kk < VEC; ++kk) {
                int ee = e + kk;
                if (ee >= E) break;
                int ii = __ldcs(map0 + ee);
                int jj = __ldcs(map1 + ee);
                int bi = __ldcs(batch + ee);
                float V;
                EDGE_V(ii, jj, V);
                HANDLE1(bi, V);
            }
        }
    }

    flush_acc(out, seg, acc);
}

// ---------------------------------------------------------------------------
// Launch: 2 kernels, int32 committed
// ---------------------------------------------------------------------------
extern "C" void kernel_launch(void* const* d_in, const int* in_sizes, int n_in,
                              void* d_out, int out_size)
{
    const float* pos        = (const float*)d_in[0];
    const float* ks         = (const float*)d_in[1];
    const float* v0t        = (const float*)d_in[2];
    const int*   mapping    = (const int*)d_in[3];
    const int*   atom_types = (const int*)d_in[4];
    const int*   batch      = (const int*)d_in[5];

    const int N = in_sizes[0] / 3;
    const int E = in_sizes[3] / 2;
    const int G = out_size;

    float* out = (float*)d_out;

    int prepThreads = (N > G) ? N : G;
    int prepBlocks  = (prepThreads + TPB - 1) / TPB;
    prep_kernel<<<prepBlocks, TPB>>>(pos, atom_types, out, N, G);

    int blocks = (E + TILE - 1) / TILE;
    edge_kernel<<<blocks, TPB>>>(mapping, mapping + E, batch, ks, v0t, out, E);
}